// round 16
// baseline (speedup 1.0000x reference)
#include <cuda_runtime.h>
#include <cuda_fp16.h>
#include <cstdint>

// ---------------- problem constants ----------------
#define BATCH 1024
#define DIM   512
#define NCLS  100000

// ---------------- GEMM tiling ----------------
#define BM 128
#define BN 128
#define BK 128                           // k per chunk
#define KCH (DIM / BK)                   // 4 chunks per c-tile
#define NBT (BATCH / BM)                 // 8 b-tiles
#define NCT ((NCLS + BN - 1) / BN)       // 782 c-tiles
#define NSTG 3
#define A_RES_BYTES (BM * DIM * 2)       // 131072: A(bt) full-K resident
#define B_STAGE (BN * BK * 2)            // 32768
#define DYN_SMEM (A_RES_BYTES + NSTG * B_STAGE)  // 229376 <= 232448 cap
#define NTHREADS 256                     // 8 warps, warp tile 64x32 (mt=4, nt=4)

// scratch (static device arrays — no allocation). Referenced ONLY in device code
// (host-side use of a __device__ symbol yields the shadow address — R7 bug).
__device__ __half g_xh[BATCH * DIM];            // normalized input, fp16-rn
__device__ __half g_wh[(size_t)NCLS * DIM];     // normalized weight, fp16-rn (102 MB)

// ---------------- helpers ----------------
__device__ __forceinline__ uint32_t smem_u32(const void* p) {
    uint32_t a;
    asm("{ .reg .u64 t; cvta.to.shared.u64 t, %1; cvt.u32.u64 %0, t; }" : "=r"(a) : "l"(p));
    return a;
}
__device__ __forceinline__ void cp16(uint32_t saddr, const void* g, bool valid) {
    int sz = valid ? 16 : 0;
    asm volatile("cp.async.cg.shared.global.L2::128B [%0], [%1], 16, %2;\n"
                 :: "r"(saddr), "l"(g), "r"(sz) : "memory");
}
__device__ __forceinline__ void ldsm_x4(uint32_t* r, uint32_t addr) {
    asm volatile("ldmatrix.sync.aligned.m8n8.x4.shared.b16 {%0,%1,%2,%3}, [%4];"
                 : "=r"(r[0]), "=r"(r[1]), "=r"(r[2]), "=r"(r[3]) : "r"(addr));
}
// m16n8k16 fp16 MMA, fp16 accumulate
__device__ __forceinline__ void mma_f16acc(uint32_t* d, const uint32_t* a, uint32_t b0, uint32_t b1) {
    asm volatile(
        "mma.sync.aligned.m16n8k16.row.col.f16.f16.f16.f16 "
        "{%0,%1}, {%2,%3,%4,%5}, {%6,%7}, {%0,%1};\n"
        : "+r"(d[0]), "+r"(d[1])
        : "r"(a[0]), "r"(a[1]), "r"(a[2]), "r"(a[3]), "r"(b0), "r"(b1));
}

// ---------------- fused row-normalize -> fp16 (warp per row, MLP=4) ----------------
__global__ void k_norm_all(const float* __restrict__ input,
                           const float* __restrict__ weight) {
    int gw = (blockIdx.x * blockDim.x + threadIdx.x) >> 5;
    int lane = threadIdx.x & 31;
    if (gw >= BATCH + NCLS) return;
    const bool isA = gw < BATCH;
    const int r = isA ? gw : gw - BATCH;
    const float* row = (isA ? input : weight) + (size_t)r * DIM;
    float4 v[4];
    #pragma unroll
    for (int i = 0; i < 4; i++) v[i] = *(const float4*)(row + lane * 4 + i * 128);
    float ss = 0.0f;
    #pragma unroll
    for (int i = 0; i < 4; i++)
        ss += v[i].x * v[i].x + v[i].y * v[i].y + v[i].z * v[i].z + v[i].w * v[i].w;
    #pragma unroll
    for (int o = 16; o; o >>= 1) ss += __shfl_xor_sync(0xffffffffu, ss, o);
    float inv = 1.0f / fmaxf(sqrtf(ss), 1e-12f);
    __half* drow = (isA ? g_xh : g_wh) + (size_t)r * DIM;   // device-side symbols
    #pragma unroll
    for (int i = 0; i < 4; i++) {
        __half2 h0 = __floats2half2_rn(v[i].x * inv, v[i].y * inv);
        __half2 h1 = __floats2half2_rn(v[i].z * inv, v[i].w * inv);
        uint2 pk;
        pk.x = *(uint32_t*)&h0;
        pk.y = *(uint32_t*)&h1;
        *(uint2*)(drow + lane * 4 + i * 128) = pk;
    }
}

// ---------------- ArcFace epilogue math ----------------
__device__ __forceinline__ float arcface(float cosv, bool tgt) {
    if (!tgt) return 30.0f * cosv;
    float s2 = fminf(fmaxf(1.0f - cosv * cosv, 0.0f), 1.0f);
    float sine = sqrtf(s2);
    float phi = cosv * 0.8775825618903728f - sine * 0.479425538604203f;
    phi = (cosv > -0.8775825618903728f) ? phi : (cosv - 7.191383079063045f);
    return 30.0f * phi;
}

// ---------------- persistent fp16 GEMM, A-resident, 64x32 warp tiles ----------------
// 8 warps in a 2(b) x 4(c) grid of 64x32 tiles: A-fragment LDSM amortized over
// nt=4 MMAs, B over mt=4 -> smem reads 192 KB/chunk (was 256 at 32x32 tiles),
// balancing the smem pipe against the tensor floor (~2048 cyc/chunk/SMSP).
// Layouts: A resident rows 1024B (64 x 16B chunks): r*1024 + ((q^(r&7))<<4).
//          B stage rows 256B (16 x 16B chunks):     r*256  + ((q^(r&7))<<4).
__global__ void __launch_bounds__(NTHREADS, 1) k_gemm(
    const int* __restrict__ label,
    float* __restrict__ out)
{
    extern __shared__ __align__(128) char dyn[];

    const int tid = threadIdx.x;
    const int lane = tid & 31;
    const int wid = tid >> 5;
    const uint32_t a_res = smem_u32(dyn);
    const uint32_t b_base = a_res + A_RES_BYTES;

    const int G8 = (gridDim.x >> 3) << 3;
    const int p = blockIdx.x;
    if (p >= G8) return;
    const int bt = p & 7;
    const int lg = p >> 3;
    const int NG = G8 >> 3;
    if (lg >= NCT) return;
    const int nct = (NCT - 1 - lg) / NG + 1;
    const int FMAX = nct * KCH;

    // warp grid 2(b) x 4(c): each warp computes 64 x 32
    const int warp_b = (wid & 1) * 64;
    const int warp_c = (wid >> 1) * 32;
    const int gid = lane >> 2;
    const int tig = lane & 3;
    const int frow = lane & 15;     // ldmatrix: row-in-16
    const int fcq = lane >> 4;      // ldmatrix: 16B k-chunk select

    // labels for this CTA's fixed b-rows (hoisted: bt constant per CTA)
    int lab0[4], lab1[4];
    #pragma unroll
    for (int mt = 0; mt < 4; mt++) {
        int r = bt * BM + warp_b + mt * 16 + gid;
        lab0[mt] = label[r];
        lab1[mt] = label[r + 8];
    }

    // ---- load A(bt) resident: 8192 x 16B cp.async (32 per thread) ----
    #pragma unroll
    for (int i = 0; i < 32; i++) {
        int op = tid + i * NTHREADS;
        int r = op >> 6, q = op & 63;       // 64 chunks (16B) per 1024B row
        uint32_t sa = a_res + r * 1024 + ((q ^ (r & 7)) << 4);
        cp16(sa, g_xh + (bt * BM + r) * DIM + q * 8, true);
    }
    asm volatile("cp.async.commit_group;" ::: "memory");
    asm volatile("cp.async.wait_group 0;" ::: "memory");
    __syncthreads();

    float acc[4][4][4];
    #pragma unroll
    for (int i = 0; i < 4; i++)
        #pragma unroll
        for (int j = 0; j < 4; j++)
            #pragma unroll
            for (int k = 0; k < 4; k++) acc[i][j][k] = 0.0f;

    // ---- B chunk loader: f -> (ct, k-chunk); 2048 x 16B cp.async (8/thread) ----
    auto load_fB = [&](int f) {
        const int ct = lg + NG * (f >> 2);
        const int k0 = (f & 3) * BK;
        const int cb = ct * BN;
        const uint32_t ab = b_base + (f % NSTG) * B_STAGE;
        #pragma unroll
        for (int l = 0; l < 8; l++) {
            int op = tid + l * NTHREADS;
            int r = op >> 4, q = op & 15;   // 16 chunks (16B) per 256B row
            int cc = cb + r;
            uint32_t sa = ab + r * 256 + ((q ^ (r & 7)) << 4);
            cp16(sa, g_wh + (size_t)cc * DIM + k0 + q * 8, cc < NCLS);
        }
    };

    // prologue: 2 stages in flight
    load_fB(0);
    asm volatile("cp.async.commit_group;" ::: "memory");
    if (FMAX > 1) load_fB(1);
    asm volatile("cp.async.commit_group;" ::: "memory");

    uint32_t hacc[4][4][2];

    for (int f = 0; f < FMAX; f++) {
        asm volatile("cp.async.wait_group 1;" ::: "memory");
        __syncthreads();   // orders prior-iteration smem reads before stage overwrite

        if (f + 2 < FMAX) load_fB(f + 2);
        asm volatile("cp.async.commit_group;" ::: "memory");

        const uint32_t b_stage = b_base + (f % NSTG) * B_STAGE;
        const int chunk = f & 3;

        #pragma unroll
        for (int i = 0; i < 4; i++)
            #pragma unroll
            for (int j = 0; j < 4; j++) { hacc[i][j][0] = 0u; hacc[i][j][1] = 0u; }

        #pragma unroll
        for (int s = 0; s < 8; s++) {           // 8 x k16 steps per 128-chunk
            const int qb = 2 * s + fcq;              // B stage 16B-chunk [0,16)
            const int qa = chunk * 16 + 2 * s + fcq; // A resident 16B-chunk [0,64)
            uint32_t bf[2][4];
            #pragma unroll
            for (int pp = 0; pp < 2; pp++) {
                int r = warp_c + pp * 16 + frow;
                uint32_t addr = b_stage + r * 256 + ((qb ^ (r & 7)) << 4);
                ldsm_x4(bf[pp], addr);
            }
            #pragma unroll
            for (int mt = 0; mt < 4; mt++) {
                int r = warp_b + mt * 16 + frow;
                uint32_t addr = a_res + r * 1024 + ((qa ^ (r & 7)) << 4);
                uint32_t af[4];
                ldsm_x4(af, addr);
                #pragma unroll
                for (int nt = 0; nt < 4; nt++)
                    mma_f16acc(hacc[mt][nt], af, bf[nt >> 1][nt & 1], bf[nt >> 1][(nt & 1) + 2]);
            }
        }

        // flush fp16 chunk accs (128-k window) into fp32 accumulators
        #pragma unroll
        for (int mt = 0; mt < 4; mt++)
            #pragma unroll
            for (int nt = 0; nt < 4; nt++) {
                float2 f0 = __half22float2(*(__half2*)&hacc[mt][nt][0]);
                float2 f1 = __half22float2(*(__half2*)&hacc[mt][nt][1]);
                acc[mt][nt][0] += f0.x;
                acc[mt][nt][1] += f0.y;
                acc[mt][nt][2] += f1.x;
                acc[mt][nt][3] += f1.y;
            }

        if (chunk == 3) {
            // ---- fused ArcFace epilogue for finished c-tile (regs+gmem only) ----
            const int cb = (lg + NG * (f >> 2)) * BN;
            #pragma unroll
            for (int mt = 0; mt < 4; mt++) {
                int r = bt * BM + warp_b + mt * 16 + gid;
                #pragma unroll
                for (int nt = 0; nt < 4; nt++) {
                    int c = cb + warp_c + nt * 8 + 2 * tig;
                    if (c >= NCLS) continue;  // c even, NCLS even -> c+1 valid when c < NCLS
                    float2 o0, o1;
                    o0.x = arcface(acc[mt][nt][0], lab0[mt] == c);
                    o0.y = arcface(acc[mt][nt][1], lab0[mt] == c + 1);
                    o1.x = arcface(acc[mt][nt][2], lab1[mt] == c);
                    o1.y = arcface(acc[mt][nt][3], lab1[mt] == c + 1);
                    *(float2*)(out + (size_t)r * NCLS + c) = o0;
                    *(float2*)(out + (size_t)(r + 8) * NCLS + c) = o1;
                    acc[mt][nt][0] = 0.0f; acc[mt][nt][1] = 0.0f;
                    acc[mt][nt][2] = 0.0f; acc[mt][nt][3] = 0.0f;
                }
            }
        }
    }
}

extern "C" void kernel_launch(void* const* d_in, const int* in_sizes, int n_in,
                              void* d_out, int out_size) {
    const float* input  = (const float*)d_in[0];
    const int*   label  = (const int*)d_in[1];
    const float* weight = (const float*)d_in[2];
    float* out = (float*)d_out;

    cudaFuncSetAttribute(k_gemm, cudaFuncAttributeMaxDynamicSharedMemorySize, DYN_SMEM);

    int nsm = 148;
    cudaDeviceGetAttribute(&nsm, cudaDevAttrMultiProcessorCount, 0);
    int grid = (nsm / 8) * 8;   // multiple of 8 for the bt x group decomposition

    // single fused normalize pass (input + weight), warp per row
    int nwarps = BATCH + NCLS;
    k_norm_all<<<(nwarps * 32 + 255) / 256, 256>>>(input, weight);
    k_gemm<<<grid, NTHREADS, DYN_SMEM>>>(label, out);
}